// round 15
// baseline (speedup 1.0000x reference)
#include <cuda_runtime.h>
#include <cuda_fp16.h>
#include <cstdint>

// Problem constants
#define BATCH 2
#define SEQ   2048
#define DMODEL 1024
#define NHEADS 16
#define DHEAD 64
#define TOTDIM 1024          // NHEADS*DHEAD
#define E3 3072              // 3*TOTDIM
#define MTOT (BATCH*SEQ)     // 4096

// ---------------------------------------------------------------------------
// Scratch (static device globals — runtime alloc is forbidden)
// ---------------------------------------------------------------------------
__device__ __half g_qkvh[(size_t)MTOT * E3];     // [4096,3072] fp16
__device__ __half g_xh[(size_t)MTOT * DMODEL];
__device__ __half g_wqh[(size_t)E3 * DMODEL];
__device__ __half g_woh[(size_t)TOTDIM * DMODEL];
__device__ __half g_ah[(size_t)MTOT * TOTDIM];   // attention output fp16

// ---------------------------------------------------------------------------
// Portable PTX helpers (no sm_103a-only features)
// ---------------------------------------------------------------------------
__device__ __forceinline__ uint32_t smem_to_u32(const void* p) {
    uint32_t a;
    asm("{ .reg .u64 t; cvta.to.shared.u64 t, %1; cvt.u32.u64 %0, t; }" : "=r"(a) : "l"(p));
    return a;
}

__device__ __forceinline__ void ldmx4(uint32_t* r, uint32_t addr) {
    asm volatile("ldmatrix.sync.aligned.m8n8.x4.shared.b16 {%0,%1,%2,%3}, [%4];"
        : "=r"(r[0]), "=r"(r[1]), "=r"(r[2]), "=r"(r[3]) : "r"(addr));
}

__device__ __forceinline__ void ldmx4t(uint32_t* r, uint32_t addr) {
    asm volatile("ldmatrix.sync.aligned.m8n8.x4.trans.shared.b16 {%0,%1,%2,%3}, [%4];"
        : "=r"(r[0]), "=r"(r[1]), "=r"(r[2]), "=r"(r[3]) : "r"(addr));
}

__device__ __forceinline__ void mma_f16(float* d, const uint32_t* a, uint32_t b0, uint32_t b1) {
    asm volatile("mma.sync.aligned.m16n8k16.row.col.f32.f16.f16.f32 "
        "{%0,%1,%2,%3}, {%4,%5,%6,%7}, {%8,%9}, {%0,%1,%2,%3};"
        : "+f"(d[0]), "+f"(d[1]), "+f"(d[2]), "+f"(d[3])
        : "r"(a[0]), "r"(a[1]), "r"(a[2]), "r"(a[3]), "r"(b0), "r"(b1));
}

__device__ __forceinline__ void cp16(uint32_t dst, const void* src) {
    asm volatile("cp.async.cg.shared.global [%0], [%1], 16;" :: "r"(dst), "l"(src));
}
#define CP_COMMIT() asm volatile("cp.async.commit_group;" ::: "memory")
#define CP_WAIT(n)  asm volatile("cp.async.wait_group %0;" :: "n"(n) : "memory")

__device__ __forceinline__ uint32_t pack_h2(float x, float y) {
    __half2 h = __floats2half2_rn(x, y);
    return *(uint32_t*)&h;
}

__device__ __forceinline__ uint32_t hmul2_u32(uint32_t a, uint32_t b) {
    __half2 r = __hmul2(*(__half2*)&a, *(__half2*)&b);
    return *(uint32_t*)&r;
}

// exp2 on packed half2: one MUFU op for two values; returns packed fp16 p and
// accumulates their fp32 sum.
__device__ __forceinline__ uint32_t exp2_pair(float t0, float t1, float& sum) {
    uint32_t packed = pack_h2(t0, t1);
    __half2 pe = h2exp2(*(__half2*)&packed);
    float2 f2 = __half22float2(pe);
    sum += f2.x + f2.y;
    return *(uint32_t*)&pe;
}

#define SWZ(r, off) ((uint32_t)(off) ^ (uint32_t)(((r) & 7) << 4))

// ---------------------------------------------------------------------------
// Fused convert: x, Wqkv, Wout -> fp16 in one launch
// ---------------------------------------------------------------------------
#define NX4 (MTOT * DMODEL / 4)
#define NQ4 (E3 * DMODEL / 4)
#define NO4 (TOTDIM * DMODEL / 4)
#define NTOT4 (NX4 + NQ4 + NO4)

__global__ void to_fp16_all(const float* __restrict__ x, const float* __restrict__ wq,
                            const float* __restrict__ wo, __half* __restrict__ xh,
                            __half* __restrict__ wqh, __half* __restrict__ woh)
{
    int i = blockIdx.x * blockDim.x + threadIdx.x;
    if (i >= NTOT4) return;
    const float* src;
    __half* dst;
    int j;
    if (i < NX4)            { src = x;  dst = xh;  j = i; }
    else if (i < NX4 + NQ4) { src = wq; dst = wqh; j = i - NX4; }
    else                    { src = wo; dst = woh; j = i - NX4 - NQ4; }
    float4 v = ((const float4*)src)[j];
    uint2 o;
    o.x = pack_h2(v.x, v.y);
    o.y = pack_h2(v.z, v.w);
    ((uint2*)dst)[j] = o;
}

// ---------------------------------------------------------------------------
// GEMM: C[M,N] = A[M,K] @ B[N,K]^T, fp16 in, fp32 accum. (R13 version)
// CTA tile 256x128, 8 warps (4m x 2n), warp tile 64x64; K-stage 128.
// ---------------------------------------------------------------------------
#define OA_P 32768
#define OB0  65536
#define OB_P 16384
#define STAGE_BYTES 98304
#define GSMEM (2 * STAGE_BYTES)

template<bool OUT_HALF>
__global__ __launch_bounds__(256, 1)
void gemm_mma_f16(const __half* __restrict__ A, const __half* __restrict__ B,
                  float* __restrict__ C, __half* __restrict__ Ch, int Nn, int K)
{
    extern __shared__ char sm[];
    const uint32_t sbase = smem_to_u32(sm);

    const int tid  = threadIdx.x;
    const int wid  = tid >> 5;
    const int lane = tid & 31;
    const int warp_m = wid & 3;
    const int warp_n = wid >> 2;
    const int row0 = blockIdx.y * 256;
    const int col0 = blockIdx.x * 128;

    const __half* gA = A + (size_t)row0 * K;
    const __half* gB = B + (size_t)col0 * K;

    float acc[4][8][4];
#pragma unroll
    for (int m = 0; m < 4; ++m)
#pragma unroll
        for (int n = 0; n < 8; ++n)
#pragma unroll
            for (int r = 0; r < 4; ++r) acc[m][n][r] = 0.f;

    const int ld_r = lane & 15;
    const int ld_k = (lane >> 4) * 16;
    const int nst = K / 128;

    auto issue = [&](int c, int s) {
        const uint32_t st = sbase + (uint32_t)s * STAGE_BYTES;
#pragma unroll
        for (int p = 0; p < 2; ++p) {
            const int kc = c * 128 + p * 64;
#pragma unroll
            for (int i = 0; i < 8; ++i) {
                const int idx = i * 256 + tid;
                const int r = idx >> 3;
                const int cb = (idx & 7) * 16;
                const uint32_t off = SWZ(r, r * 128 + cb);
                cp16(st + p * OA_P + off, (const char*)(gA + (size_t)r * K + kc) + cb);
            }
#pragma unroll
            for (int i = 0; i < 4; ++i) {
                const int idx = i * 256 + tid;
                const int r = idx >> 3;
                const int cb = (idx & 7) * 16;
                const uint32_t off = SWZ(r, r * 128 + cb);
                cp16(st + OB0 + p * OB_P + off, (const char*)(gB + (size_t)r * K + kc) + cb);
            }
        }
        CP_COMMIT();
    };

    issue(0, 0);

    for (int c = 0; c < nst; ++c) {
        const int s = c & 1;
        if (c + 1 < nst) { issue(c + 1, (c + 1) & 1); CP_WAIT(1); }
        else             { CP_WAIT(0); }
        __syncthreads();

        const uint32_t st = sbase + (uint32_t)s * STAGE_BYTES;
#pragma unroll
        for (int p = 0; p < 2; ++p) {
#pragma unroll
            for (int ks = 0; ks < 4; ++ks) {
                uint32_t bf[4][4];
#pragma unroll
                for (int nt2 = 0; nt2 < 4; ++nt2) {
                    const int r = warp_n * 64 + nt2 * 16 + ld_r;
                    uint32_t off = SWZ(r, r * 128 + ks * 32 + ld_k);
                    ldmx4(bf[nt2], st + OB0 + p * OB_P + off);
                }
#pragma unroll
                for (int mt = 0; mt < 4; ++mt) {
                    uint32_t af[4];
                    const int r = warp_m * 64 + mt * 16 + ld_r;
                    uint32_t off = SWZ(r, r * 128 + ks * 32 + ld_k);
                    ldmx4(af, st + p * OA_P + off);
#pragma unroll
                    for (int nt = 0; nt < 8; ++nt) {
                        const int n2 = nt >> 1, nb = nt & 1;
                        mma_f16(acc[mt][nt], af, bf[n2][nb], bf[n2][nb + 2]);
                    }
                }
            }
        }
        __syncthreads();
    }

    const int grp = lane >> 2;
    const int qid = (lane & 3) * 2;
#pragma unroll
    for (int mt = 0; mt < 4; ++mt) {
        const int gm = row0 + warp_m * 64 + mt * 16 + grp;
#pragma unroll
        for (int nt = 0; nt < 8; ++nt) {
            const int gn = col0 + warp_n * 64 + nt * 8 + qid;
            if (OUT_HALF) {
                *(uint32_t*)(Ch + (size_t)gm * Nn + gn)       = pack_h2(acc[mt][nt][0], acc[mt][nt][1]);
                *(uint32_t*)(Ch + (size_t)(gm + 8) * Nn + gn) = pack_h2(acc[mt][nt][2], acc[mt][nt][3]);
            } else {
                *(float2*)(C + (size_t)gm * Nn + gn)       = make_float2(acc[mt][nt][0], acc[mt][nt][1]);
                *(float2*)(C + (size_t)(gm + 8) * Nn + gn) = make_float2(acc[mt][nt][2], acc[mt][nt][3]);
            }
        }
    }
}

// ---------------------------------------------------------------------------
// Tensor-core flash attention (causal), fp16, fp32 accum.
// CTA = 128 queries, 256 threads / 8 warps, each warp owns 16 q-rows
// (same per-warp register footprint as the proven 64-query kernel).
// 64-key tiles; cp.async 2-stage K/V pipe; log2-domain softmax.
// Smem: Q 16K | 2 stages x (K 8K | V 8K) = 48 KB.
// ---------------------------------------------------------------------------
#define ATT_SMEM 49152
#define AKV(s)  (16384 + (s) * 16384)

__global__ __launch_bounds__(256, 2)
void attn_mma(const __half* __restrict__ qkv, __half* __restrict__ ao)
{
    extern __shared__ char sm[];
    const uint32_t sb = smem_to_u32(sm);

    const int tid = threadIdx.x;
    const int wid = tid >> 5, lane = tid & 31;
    const int grp = lane >> 2, qid = lane & 3;
    const int qt = gridDim.x - 1 - blockIdx.x;      // longest-job-first
    const int bh = blockIdx.y;
    const int b = bh >> 4, h = bh & 15;
    const int qb = qt * 128;
    const int qr = wid * 16;

    const char* qpb = (const char*)(qkv + (size_t)(b * SEQ) * E3 + h * DHEAD);
    const char* kpb = qpb + TOTDIM * 2;
    const char* vpb = qpb + 2 * TOTDIM * 2;
    const size_t rstride = (size_t)E3 * 2;   // bytes per token row

    // ---- Load Q tile (128 rows) ----
#pragma unroll
    for (int i = 0; i < 4; ++i) {
        const int idx = i * 256 + tid;          // 0..1023
        const int r = idx >> 3;                 // 0..127
        const int c = (idx & 7) * 16;
        const uint32_t off = SWZ(r, r * 128 + c);
        *(uint4*)(sm + off) = *(const uint4*)(qpb + (size_t)(qb + r) * rstride + c);
    }

    auto issue_kv = [&](int jt, int s) {
        const int kb = jt * 64;
        const uint32_t st = sb + AKV(s);
#pragma unroll
        for (int i = 0; i < 2; ++i) {
            const int idx = i * 256 + tid;      // 0..511
            const int r = idx >> 3;             // 0..63
            const int c = (idx & 7) * 16;
            const uint32_t off = SWZ(r, r * 128 + c);
            const size_t gofs = (size_t)(kb + r) * rstride + c;
            cp16(st + off,        kpb + gofs);
            cp16(st + 8192 + off, vpb + gofs);
        }
        CP_COMMIT();
    };

    issue_kv(0, 0);
    __syncthreads();   // Q visible

    // ---- Hoist Q A-fragments, pre-scaled by 0.125*log2(e) ----
    uint32_t aq[4][4];
    {
        const __half2 sc2 = __half2half2(__float2half(0.125f * 1.44269504f));
        const uint32_t scu = *(const uint32_t*)&sc2;
        const int r = qr + (lane & 15);
        const int ch = (lane >> 4) << 4;
#pragma unroll
        for (int ks = 0; ks < 4; ++ks) {
            uint32_t off = SWZ(r, r * 128 + ks * 32 + ch);
            ldmx4(aq[ks], sb + off);
#pragma unroll
            for (int j = 0; j < 4; ++j) aq[ks][j] = hmul2_u32(aq[ks][j], scu);
        }
    }

    float o[8][4];
#pragma unroll
    for (int nd = 0; nd < 8; ++nd)
#pragma unroll
        for (int i = 0; i < 4; ++i) o[nd][i] = 0.f;
    float m0 = -1e30f, m1 = -1e30f, l0 = 0.f, l1 = 0.f;

    const int nkt = 2 * qt + 2;     // key tiles covering rows [qb, qb+128)

    for (int jt = 0; jt < nkt; ++jt) {
        const int kb = jt * 64;
        const int s = jt & 1;
        if (jt + 1 < nkt) { issue_kv(jt + 1, (jt + 1) & 1); CP_WAIT(1); }
        else              { CP_WAIT(0); }
        __syncthreads();

        const uint32_t st = sb + AKV(s);

        // ---- S = (Q*0.125*log2e) @ K^T  (S in log2 units) ----
        float sacc[8][4];
#pragma unroll
        for (int nb = 0; nb < 8; ++nb)
#pragma unroll
            for (int i = 0; i < 4; ++i) sacc[nb][i] = 0.f;
        {
            const int rB = lane & 15;
            const int chB = (lane >> 4) << 4;
#pragma unroll
            for (int ks = 0; ks < 4; ++ks) {
                uint32_t kf[4][4];
#pragma unroll
                for (int nt2 = 0; nt2 < 4; ++nt2) {
                    const int r = nt2 * 16 + rB;
                    uint32_t off = SWZ(r, r * 128 + ks * 32 + chB);
                    ldmx4(kf[nt2], st + off);
                }
#pragma unroll
                for (int nt2 = 0; nt2 < 4; ++nt2)
#pragma unroll
                    for (int j = 0; j < 2; ++j)
                        mma_f16(sacc[nt2 * 2 + j], aq[ks], kf[nt2][j], kf[nt2][j + 2]);
            }
        }

        // ---- Causal mask (diagonal-crossing tiles only) ----
        if (jt >= 2 * qt) {
            const int row0g = qb + qr + grp;
            const int row1g = row0g + 8;
#pragma unroll
            for (int nb = 0; nb < 8; ++nb) {
                const int c0 = kb + nb * 8 + qid * 2;
                if (c0 > row0g)     sacc[nb][0] = -1e30f;
                if (c0 + 1 > row0g) sacc[nb][1] = -1e30f;
                if (c0 > row1g)     sacc[nb][2] = -1e30f;
                if (c0 + 1 > row1g) sacc[nb][3] = -1e30f;
            }
        }

        // ---- Online softmax (log2 domain) ----
        float mx0 = -1e30f, mx1 = -1e30f;
#pragma unroll
        for (int nb = 0; nb < 8; ++nb) {
            mx0 = fmaxf(mx0, fmaxf(sacc[nb][0], sacc[nb][1]));
            mx1 = fmaxf(mx1, fmaxf(sacc[nb][2], sacc[nb][3]));
        }
        mx0 = fmaxf(mx0, __shfl_xor_sync(0xffffffffu, mx0, 1));
        mx0 = fmaxf(mx0, __shfl_xor_sync(0xffffffffu, mx0, 2));
        mx1 = fmaxf(mx1, __shfl_xor_sync(0xffffffffu, mx1, 1));
        mx1 = fmaxf(mx1, __shfl_xor_sync(0xffffffffu, mx1, 2));
        const float mn0 = fmaxf(m0, mx0), mn1 = fmaxf(m1, mx1);
        const float f0 = exp2f(m0 - mn0), f1 = exp2f(m1 - mn1);
        m0 = mn0; m1 = mn1;

        // ---- P = exp2(S - m) as fp16 fragments + row sums ----
        float sum0 = 0.f, sum1 = 0.f;
        uint32_t pf[4][4];
#pragma unroll
        for (int kp = 0; kp < 4; ++kp) {
            pf[kp][0] = exp2_pair(sacc[2*kp][0] - m0,   sacc[2*kp][1] - m0,   sum0);
            pf[kp][1] = exp2_pair(sacc[2*kp][2] - m1,   sacc[2*kp][3] - m1,   sum1);
            pf[kp][2] = exp2_pair(sacc[2*kp+1][0] - m0, sacc[2*kp+1][1] - m0, sum0);
            pf[kp][3] = exp2_pair(sacc[2*kp+1][2] - m1, sacc[2*kp+1][3] - m1, sum1);
        }
        sum0 += __shfl_xor_sync(0xffffffffu, sum0, 1);
        sum0 += __shfl_xor_sync(0xffffffffu, sum0, 2);
        sum1 += __shfl_xor_sync(0xffffffffu, sum1, 1);
        sum1 += __shfl_xor_sync(0xffffffffu, sum1, 2);
        l0 = l0 * f0 + sum0;
        l1 = l1 * f1 + sum1;
#pragma unroll
        for (int nd = 0; nd < 8; ++nd) {
            o[nd][0] *= f0; o[nd][1] *= f0;
            o[nd][2] *= f1; o[nd][3] *= f1;
        }

        // ---- O += P @ V ; V^T B-frags via ldmatrix.trans ----
        {
            const int tile = lane >> 3;
            const int ta = tile & 1, ndo = tile >> 1;
            const int rl = lane & 7;
#pragma unroll
            for (int kp = 0; kp < 4; ++kp) {
#pragma unroll
                for (int ndp = 0; ndp < 4; ++ndp) {
                    const int r = kp * 16 + ta * 8 + rl;
                    uint32_t off = SWZ(r, r * 128 + (ndp * 2 + ndo) * 16);
                    uint32_t vf[4];
                    ldmx4t(vf, st + 8192 + off);
                    mma_f16(o[ndp*2],   pf[kp], vf[0], vf[1]);
                    mma_f16(o[ndp*2+1], pf[kp], vf[2], vf[3]);
                }
            }
        }
        __syncthreads();   // stage consumed
    }

    // ---- Epilogue: normalize, store fp16 ----
    const float inv0 = 1.f / l0, inv1 = 1.f / l1;
    const int row0g = qb + qr + grp;
    const size_t base0 = (size_t)(b * SEQ + row0g) * TOTDIM + h * DHEAD;
    const size_t base1 = base0 + (size_t)8 * TOTDIM;
#pragma unroll
    for (int nd = 0; nd < 8; ++nd) {
        const int col = nd * 8 + qid * 2;
        *(uint32_t*)(ao + base0 + col) = pack_h2(o[nd][0] * inv0, o[nd][1] * inv0);
        *(uint32_t*)(ao + base1 + col) = pack_h2(o[nd][2] * inv1, o[nd][3] * inv1);
    }
}

// ---------------------------------------------------------------------------
extern "C" void kernel_launch(void* const* d_in, const int* in_sizes, int n_in,
                              void* d_out, int out_size)
{
    const float* x    = (const float*)d_in[0];   // [2,2048,1024]
    const float* Wqkv = (const float*)d_in[1];   // [3072,1024]
    const float* Wout = (const float*)d_in[2];   // [1024,1024]
    float* out = (float*)d_out;                  // [2,2048,1024]

    __half *qkvh, *xh, *wqh, *woh, *ah;
    cudaGetSymbolAddress((void**)&qkvh, g_qkvh);
    cudaGetSymbolAddress((void**)&xh,  g_xh);
    cudaGetSymbolAddress((void**)&wqh, g_wqh);
    cudaGetSymbolAddress((void**)&woh, g_woh);
    cudaGetSymbolAddress((void**)&ah,  g_ah);

    cudaFuncSetAttribute(gemm_mma_f16<true>,  cudaFuncAttributeMaxDynamicSharedMemorySize, GSMEM);
    cudaFuncSetAttribute(gemm_mma_f16<false>, cudaFuncAttributeMaxDynamicSharedMemorySize, GSMEM);
    cudaFuncSetAttribute(attn_mma, cudaFuncAttributeMaxDynamicSharedMemorySize, ATT_SMEM);

    // Convert all inputs to fp16 in one launch
    to_fp16_all<<<(NTOT4 + 255) / 256, 256>>>(x, Wqkv, Wout, xh, wqh, woh);

    // 1) qkv = x @ Wqkv^T : [4096, 3072] -> fp16
    gemm_mma_f16<true><<<dim3(E3/128, MTOT/256), 256, GSMEM>>>(
        xh, wqh, nullptr, qkvh, E3, DMODEL);

    // 2) causal attention -> fp16 [4096, 1024]
    attn_mma<<<dim3(SEQ/128, BATCH*NHEADS), 256, ATT_SMEM>>>(qkvh, ah);

    // 3) out = attn @ Wout^T : [4096, 1024] -> fp32
    gemm_mma_f16<false><<<dim3(TOTDIM/128, MTOT/256), 256, GSMEM>>>(
        ah, woh, out, nullptr, TOTDIM, DMODEL);
}

// round 16
// speedup vs baseline: 1.0701x; 1.0701x over previous
#include <cuda_runtime.h>
#include <cuda_fp16.h>
#include <cstdint>

// Problem constants
#define BATCH 2
#define SEQ   2048
#define DMODEL 1024
#define NHEADS 16
#define DHEAD 64
#define TOTDIM 1024          // NHEADS*DHEAD
#define E3 3072              // 3*TOTDIM
#define MTOT (BATCH*SEQ)     // 4096

// ---------------------------------------------------------------------------
// Scratch (static device globals — runtime alloc is forbidden)
// ---------------------------------------------------------------------------
__device__ __half g_qkvh[(size_t)MTOT * E3];     // [4096,3072] fp16
__device__ __half g_xh[(size_t)MTOT * DMODEL];
__device__ __half g_wqh[(size_t)E3 * DMODEL];
__device__ __half g_woh[(size_t)TOTDIM * DMODEL];
__device__ __half g_ah[(size_t)MTOT * TOTDIM];   // attention output fp16

// ---------------------------------------------------------------------------
// Portable PTX helpers (no sm_103a-only features)
// ---------------------------------------------------------------------------
__device__ __forceinline__ uint32_t smem_to_u32(const void* p) {
    uint32_t a;
    asm("{ .reg .u64 t; cvta.to.shared.u64 t, %1; cvt.u32.u64 %0, t; }" : "=r"(a) : "l"(p));
    return a;
}

__device__ __forceinline__ void ldmx4(uint32_t* r, uint32_t addr) {
    asm volatile("ldmatrix.sync.aligned.m8n8.x4.shared.b16 {%0,%1,%2,%3}, [%4];"
        : "=r"(r[0]), "=r"(r[1]), "=r"(r[2]), "=r"(r[3]) : "r"(addr));
}

__device__ __forceinline__ void ldmx4t(uint32_t* r, uint32_t addr) {
    asm volatile("ldmatrix.sync.aligned.m8n8.x4.trans.shared.b16 {%0,%1,%2,%3}, [%4];"
        : "=r"(r[0]), "=r"(r[1]), "=r"(r[2]), "=r"(r[3]) : "r"(addr));
}

__device__ __forceinline__ void mma_f16(float* d, const uint32_t* a, uint32_t b0, uint32_t b1) {
    asm volatile("mma.sync.aligned.m16n8k16.row.col.f32.f16.f16.f32 "
        "{%0,%1,%2,%3}, {%4,%5,%6,%7}, {%8,%9}, {%0,%1,%2,%3};"
        : "+f"(d[0]), "+f"(d[1]), "+f"(d[2]), "+f"(d[3])
        : "r"(a[0]), "r"(a[1]), "r"(a[2]), "r"(a[3]), "r"(b0), "r"(b1));
}

__device__ __forceinline__ void cp16(uint32_t dst, const void* src) {
    asm volatile("cp.async.cg.shared.global [%0], [%1], 16;" :: "r"(dst), "l"(src));
}
#define CP_COMMIT() asm volatile("cp.async.commit_group;" ::: "memory")
#define CP_WAIT(n)  asm volatile("cp.async.wait_group %0;" :: "n"(n) : "memory")

__device__ __forceinline__ uint32_t pack_h2(float x, float y) {
    __half2 h = __floats2half2_rn(x, y);
    return *(uint32_t*)&h;
}

__device__ __forceinline__ uint32_t hmul2_u32(uint32_t a, uint32_t b) {
    __half2 r = __hmul2(*(__half2*)&a, *(__half2*)&b);
    return *(uint32_t*)&r;
}

// exp2 on packed half2: one MUFU op for two values; returns packed fp16 p and
// accumulates their fp32 sum.
__device__ __forceinline__ uint32_t exp2_pair(float t0, float t1, float& sum) {
    uint32_t packed = pack_h2(t0, t1);
    __half2 pe = h2exp2(*(__half2*)&packed);
    float2 f2 = __half22float2(pe);
    sum += f2.x + f2.y;
    return *(uint32_t*)&pe;
}

#define SWZ(r, off) ((uint32_t)(off) ^ (uint32_t)(((r) & 7) << 4))

// ---------------------------------------------------------------------------
// Fused convert: x, Wqkv, Wout -> fp16 in one launch
// ---------------------------------------------------------------------------
#define NX4 (MTOT * DMODEL / 4)
#define NQ4 (E3 * DMODEL / 4)
#define NO4 (TOTDIM * DMODEL / 4)
#define NTOT4 (NX4 + NQ4 + NO4)

__global__ void to_fp16_all(const float* __restrict__ x, const float* __restrict__ wq,
                            const float* __restrict__ wo, __half* __restrict__ xh,
                            __half* __restrict__ wqh, __half* __restrict__ woh)
{
    int i = blockIdx.x * blockDim.x + threadIdx.x;
    if (i >= NTOT4) return;
    const float* src;
    __half* dst;
    int j;
    if (i < NX4)            { src = x;  dst = xh;  j = i; }
    else if (i < NX4 + NQ4) { src = wq; dst = wqh; j = i - NX4; }
    else                    { src = wo; dst = woh; j = i - NX4 - NQ4; }
    float4 v = ((const float4*)src)[j];
    uint2 o;
    o.x = pack_h2(v.x, v.y);
    o.y = pack_h2(v.z, v.w);
    ((uint2*)dst)[j] = o;
}

// ---------------------------------------------------------------------------
// GEMM: C[M,N] = A[M,K] @ B[N,K]^T, fp16 in, fp32 accum. (R13 version)
// CTA tile 256x128, 8 warps (4m x 2n), warp tile 64x64; K-stage 128.
// ---------------------------------------------------------------------------
#define OA_P 32768
#define OB0  65536
#define OB_P 16384
#define STAGE_BYTES 98304
#define GSMEM (2 * STAGE_BYTES)

template<bool OUT_HALF>
__global__ __launch_bounds__(256, 1)
void gemm_mma_f16(const __half* __restrict__ A, const __half* __restrict__ B,
                  float* __restrict__ C, __half* __restrict__ Ch, int Nn, int K)
{
    extern __shared__ char sm[];
    const uint32_t sbase = smem_to_u32(sm);

    const int tid  = threadIdx.x;
    const int wid  = tid >> 5;
    const int lane = tid & 31;
    const int warp_m = wid & 3;
    const int warp_n = wid >> 2;
    const int row0 = blockIdx.y * 256;
    const int col0 = blockIdx.x * 128;

    const __half* gA = A + (size_t)row0 * K;
    const __half* gB = B + (size_t)col0 * K;

    float acc[4][8][4];
#pragma unroll
    for (int m = 0; m < 4; ++m)
#pragma unroll
        for (int n = 0; n < 8; ++n)
#pragma unroll
            for (int r = 0; r < 4; ++r) acc[m][n][r] = 0.f;

    const int ld_r = lane & 15;
    const int ld_k = (lane >> 4) * 16;
    const int nst = K / 128;

    auto issue = [&](int c, int s) {
        const uint32_t st = sbase + (uint32_t)s * STAGE_BYTES;
#pragma unroll
        for (int p = 0; p < 2; ++p) {
            const int kc = c * 128 + p * 64;
#pragma unroll
            for (int i = 0; i < 8; ++i) {
                const int idx = i * 256 + tid;
                const int r = idx >> 3;
                const int cb = (idx & 7) * 16;
                const uint32_t off = SWZ(r, r * 128 + cb);
                cp16(st + p * OA_P + off, (const char*)(gA + (size_t)r * K + kc) + cb);
            }
#pragma unroll
            for (int i = 0; i < 4; ++i) {
                const int idx = i * 256 + tid;
                const int r = idx >> 3;
                const int cb = (idx & 7) * 16;
                const uint32_t off = SWZ(r, r * 128 + cb);
                cp16(st + OB0 + p * OB_P + off, (const char*)(gB + (size_t)r * K + kc) + cb);
            }
        }
        CP_COMMIT();
    };

    issue(0, 0);

    for (int c = 0; c < nst; ++c) {
        const int s = c & 1;
        if (c + 1 < nst) { issue(c + 1, (c + 1) & 1); CP_WAIT(1); }
        else             { CP_WAIT(0); }
        __syncthreads();

        const uint32_t st = sbase + (uint32_t)s * STAGE_BYTES;
#pragma unroll
        for (int p = 0; p < 2; ++p) {
#pragma unroll
            for (int ks = 0; ks < 4; ++ks) {
                uint32_t bf[4][4];
#pragma unroll
                for (int nt2 = 0; nt2 < 4; ++nt2) {
                    const int r = warp_n * 64 + nt2 * 16 + ld_r;
                    uint32_t off = SWZ(r, r * 128 + ks * 32 + ld_k);
                    ldmx4(bf[nt2], st + OB0 + p * OB_P + off);
                }
#pragma unroll
                for (int mt = 0; mt < 4; ++mt) {
                    uint32_t af[4];
                    const int r = warp_m * 64 + mt * 16 + ld_r;
                    uint32_t off = SWZ(r, r * 128 + ks * 32 + ld_k);
                    ldmx4(af, st + p * OA_P + off);
#pragma unroll
                    for (int nt = 0; nt < 8; ++nt) {
                        const int n2 = nt >> 1, nb = nt & 1;
                        mma_f16(acc[mt][nt], af, bf[n2][nb], bf[n2][nb + 2]);
                    }
                }
            }
        }
        __syncthreads();
    }

    const int grp = lane >> 2;
    const int qid = (lane & 3) * 2;
#pragma unroll
    for (int mt = 0; mt < 4; ++mt) {
        const int gm = row0 + warp_m * 64 + mt * 16 + grp;
#pragma unroll
        for (int nt = 0; nt < 8; ++nt) {
            const int gn = col0 + warp_n * 64 + nt * 8 + qid;
            if (OUT_HALF) {
                *(uint32_t*)(Ch + (size_t)gm * Nn + gn)       = pack_h2(acc[mt][nt][0], acc[mt][nt][1]);
                *(uint32_t*)(Ch + (size_t)(gm + 8) * Nn + gn) = pack_h2(acc[mt][nt][2], acc[mt][nt][3]);
            } else {
                *(float2*)(C + (size_t)gm * Nn + gn)       = make_float2(acc[mt][nt][0], acc[mt][nt][1]);
                *(float2*)(C + (size_t)(gm + 8) * Nn + gn) = make_float2(acc[mt][nt][2], acc[mt][nt][3]);
            }
        }
    }
}

// ---------------------------------------------------------------------------
// Tensor-core flash attention (causal), fp16, fp32 accum. (R13 geometry)
// CTA = 64 queries, 128 threads / 4 warps; 64-key tiles.
// 3-stage cp.async K/V ring, ONE barrier per tile (stage slot reuse is
// protected by the top-of-loop barrier; last readers of slot (jt+2)%3 ran
// at iteration jt-1, before the barrier at jt).
// Log2-domain softmax via ex2.f16x2. Smem: Q 8K | 3 x (K 8K | V 8K) = 56 KB.
// ---------------------------------------------------------------------------
#define ATT_SMEM 57344
#define AKV(s)  (8192 + (s) * 16384)

__global__ __launch_bounds__(128, 2)
void attn_mma(const __half* __restrict__ qkv, __half* __restrict__ ao)
{
    extern __shared__ char sm[];
    const uint32_t sb = smem_to_u32(sm);

    const int tid = threadIdx.x;
    const int wid = tid >> 5, lane = tid & 31;
    const int grp = lane >> 2, qid = lane & 3;
    const int qt = gridDim.x - 1 - blockIdx.x;      // longest-job-first
    const int bh = blockIdx.y;
    const int b = bh >> 4, h = bh & 15;
    const int qb = qt * 64;
    const int qr = wid * 16;

    const char* qpb = (const char*)(qkv + (size_t)(b * SEQ) * E3 + h * DHEAD);
    const char* kpb = qpb + TOTDIM * 2;
    const char* vpb = qpb + 2 * TOTDIM * 2;
    const size_t rstride = (size_t)E3 * 2;   // bytes per token row

    // ---- Load Q tile ----
#pragma unroll
    for (int i = 0; i < 4; ++i) {
        const int idx = i * 128 + tid;          // 0..511
        const int r = idx >> 3;                 // 0..63
        const int c = (idx & 7) * 16;
        const uint32_t off = SWZ(r, r * 128 + c);
        *(uint4*)(sm + off) = *(const uint4*)(qpb + (size_t)(qb + r) * rstride + c);
    }

    auto issue_kv = [&](int jt, int s) {
        const int kb = jt * 64;
        const uint32_t st = sb + AKV(s);
#pragma unroll
        for (int i = 0; i < 4; ++i) {
            const int idx = i * 128 + tid;
            const int r = idx >> 3;
            const int c = (idx & 7) * 16;
            const uint32_t off = SWZ(r, r * 128 + c);
            const size_t gofs = (size_t)(kb + r) * rstride + c;
            cp16(st + off,        kpb + gofs);
            cp16(st + 8192 + off, vpb + gofs);
        }
        CP_COMMIT();
    };

    issue_kv(0, 0);
    if (qt >= 1) issue_kv(1, 1);
    __syncthreads();   // Q visible

    // ---- Hoist Q A-fragments, pre-scaled by 0.125*log2(e) ----
    uint32_t aq[4][4];
    {
        const __half2 sc2 = __half2half2(__float2half(0.125f * 1.44269504f));
        const uint32_t scu = *(const uint32_t*)&sc2;
        const int r = qr + (lane & 15);
        const int ch = (lane >> 4) << 4;
#pragma unroll
        for (int ks = 0; ks < 4; ++ks) {
            uint32_t off = SWZ(r, r * 128 + ks * 32 + ch);
            ldmx4(aq[ks], sb + off);
#pragma unroll
            for (int j = 0; j < 4; ++j) aq[ks][j] = hmul2_u32(aq[ks][j], scu);
        }
    }

    float o[8][4];
#pragma unroll
    for (int nd = 0; nd < 8; ++nd)
#pragma unroll
        for (int i = 0; i < 4; ++i) o[nd][i] = 0.f;
    float m0 = -1e30f, m1 = -1e30f, l0 = 0.f, l1 = 0.f;

    for (int jt = 0; jt <= qt; ++jt) {
        const int kb = jt * 64;
        const int s = jt % 3;
        if (jt < qt) { CP_WAIT(1); }     // stage jt complete; stage jt+1 may fly
        else         { CP_WAIT(0); }
        __syncthreads();                 // publish stage jt + retire slot (jt+2)%3
        if (jt + 2 <= qt) issue_kv(jt + 2, (jt + 2) % 3);

        const uint32_t st = sb + AKV(s);

        // ---- S = (Q*0.125*log2e) @ K^T  (S in log2 units) ----
        float sacc[8][4];
#pragma unroll
        for (int nb = 0; nb < 8; ++nb)
#pragma unroll
            for (int i = 0; i < 4; ++i) sacc[nb][i] = 0.f;
        {
            const int rB = lane & 15;
            const int chB = (lane >> 4) << 4;
#pragma unroll
            for (int ks = 0; ks < 4; ++ks) {
                uint32_t kf[4][4];
#pragma unroll
                for (int nt2 = 0; nt2 < 4; ++nt2) {
                    const int r = nt2 * 16 + rB;
                    uint32_t off = SWZ(r, r * 128 + ks * 32 + chB);
                    ldmx4(kf[nt2], st + off);
                }
#pragma unroll
                for (int nt2 = 0; nt2 < 4; ++nt2)
#pragma unroll
                    for (int j = 0; j < 2; ++j)
                        mma_f16(sacc[nt2 * 2 + j], aq[ks], kf[nt2][j], kf[nt2][j + 2]);
            }
        }

        // ---- Causal mask (diagonal tile only) ----
        if (jt == qt) {
            const int row0g = qb + qr + grp;
            const int row1g = row0g + 8;
#pragma unroll
            for (int nb = 0; nb < 8; ++nb) {
                const int c0 = kb + nb * 8 + qid * 2;
                if (c0 > row0g)     sacc[nb][0] = -1e30f;
                if (c0 + 1 > row0g) sacc[nb][1] = -1e30f;
                if (c0 > row1g)     sacc[nb][2] = -1e30f;
                if (c0 + 1 > row1g) sacc[nb][3] = -1e30f;
            }
        }

        // ---- Online softmax (log2 domain) ----
        float mx0 = -1e30f, mx1 = -1e30f;
#pragma unroll
        for (int nb = 0; nb < 8; ++nb) {
            mx0 = fmaxf(mx0, fmaxf(sacc[nb][0], sacc[nb][1]));
            mx1 = fmaxf(mx1, fmaxf(sacc[nb][2], sacc[nb][3]));
        }
        mx0 = fmaxf(mx0, __shfl_xor_sync(0xffffffffu, mx0, 1));
        mx0 = fmaxf(mx0, __shfl_xor_sync(0xffffffffu, mx0, 2));
        mx1 = fmaxf(mx1, __shfl_xor_sync(0xffffffffu, mx1, 1));
        mx1 = fmaxf(mx1, __shfl_xor_sync(0xffffffffu, mx1, 2));
        const float mn0 = fmaxf(m0, mx0), mn1 = fmaxf(m1, mx1);
        const float f0 = exp2f(m0 - mn0), f1 = exp2f(m1 - mn1);
        m0 = mn0; m1 = mn1;

        // ---- P = exp2(S - m) as fp16 fragments + row sums ----
        float sum0 = 0.f, sum1 = 0.f;
        uint32_t pf[4][4];
#pragma unroll
        for (int kp = 0; kp < 4; ++kp) {
            pf[kp][0] = exp2_pair(sacc[2*kp][0] - m0,   sacc[2*kp][1] - m0,   sum0);
            pf[kp][1] = exp2_pair(sacc[2*kp][2] - m1,   sacc[2*kp][3] - m1,   sum1);
            pf[kp][2] = exp2_pair(sacc[2*kp+1][0] - m0, sacc[2*kp+1][1] - m0, sum0);
            pf[kp][3] = exp2_pair(sacc[2*kp+1][2] - m1, sacc[2*kp+1][3] - m1, sum1);
        }
        sum0 += __shfl_xor_sync(0xffffffffu, sum0, 1);
        sum0 += __shfl_xor_sync(0xffffffffu, sum0, 2);
        sum1 += __shfl_xor_sync(0xffffffffu, sum1, 1);
        sum1 += __shfl_xor_sync(0xffffffffu, sum1, 2);
        l0 = l0 * f0 + sum0;
        l1 = l1 * f1 + sum1;
#pragma unroll
        for (int nd = 0; nd < 8; ++nd) {
            o[nd][0] *= f0; o[nd][1] *= f0;
            o[nd][2] *= f1; o[nd][3] *= f1;
        }

        // ---- O += P @ V ; V^T B-frags via ldmatrix.trans ----
        {
            const int tile = lane >> 3;
            const int ta = tile & 1, ndo = tile >> 1;
            const int rl = lane & 7;
#pragma unroll
            for (int kp = 0; kp < 4; ++kp) {
#pragma unroll
                for (int ndp = 0; ndp < 4; ++ndp) {
                    const int r = kp * 16 + ta * 8 + rl;
                    uint32_t off = SWZ(r, r * 128 + (ndp * 2 + ndo) * 16);
                    uint32_t vf[4];
                    ldmx4t(vf, st + 8192 + off);
                    mma_f16(o[ndp*2],   pf[kp], vf[0], vf[1]);
                    mma_f16(o[ndp*2+1], pf[kp], vf[2], vf[3]);
                }
            }
        }
        // no trailing barrier: slot reuse protected by next iteration's barrier
    }

    // ---- Epilogue: normalize, store fp16 ----
    const float inv0 = 1.f / l0, inv1 = 1.f / l1;
    const int row0g = qb + qr + grp;
    const size_t base0 = (size_t)(b * SEQ + row0g) * TOTDIM + h * DHEAD;
    const size_t base1 = base0 + (size_t)8 * TOTDIM;
#pragma unroll
    for (int nd = 0; nd < 8; ++nd) {
        const int col = nd * 8 + qid * 2;
        *(uint32_t*)(ao + base0 + col) = pack_h2(o[nd][0] * inv0, o[nd][1] * inv0);
        *(uint32_t*)(ao + base1 + col) = pack_h2(o[nd][2] * inv1, o[nd][3] * inv1);
    }
}

// ---------------------------------------------------------------------------
extern "C" void kernel_launch(void* const* d_in, const int* in_sizes, int n_in,
                              void* d_out, int out_size)
{
    const float* x    = (const float*)d_in[0];   // [2,2048,1024]
    const float* Wqkv = (const float*)d_in[1];   // [3072,1024]
    const float* Wout = (const float*)d_in[2];   // [1024,1024]
    float* out = (float*)d_out;                  // [2,2048,1024]

    __half *qkvh, *xh, *wqh, *woh, *ah;
    cudaGetSymbolAddress((void**)&qkvh, g_qkvh);
    cudaGetSymbolAddress((void**)&xh,  g_xh);
    cudaGetSymbolAddress((void**)&wqh, g_wqh);
    cudaGetSymbolAddress((void**)&woh, g_woh);
    cudaGetSymbolAddress((void**)&ah,  g_ah);

    cudaFuncSetAttribute(gemm_mma_f16<true>,  cudaFuncAttributeMaxDynamicSharedMemorySize, GSMEM);
    cudaFuncSetAttribute(gemm_mma_f16<false>, cudaFuncAttributeMaxDynamicSharedMemorySize, GSMEM);
    cudaFuncSetAttribute(attn_mma, cudaFuncAttributeMaxDynamicSharedMemorySize, ATT_SMEM);

    // Convert all inputs to fp16 in one launch
    to_fp16_all<<<(NTOT4 + 255) / 256, 256>>>(x, Wqkv, Wout, xh, wqh, woh);

    // 1) qkv = x @ Wqkv^T : [4096, 3072] -> fp16
    gemm_mma_f16<true><<<dim3(E3/128, MTOT/256), 256, GSMEM>>>(
        xh, wqh, nullptr, qkvh, E3, DMODEL);

    // 2) causal attention -> fp16 [4096, 1024]
    attn_mma<<<dim3(SEQ/64, BATCH*NHEADS), 128, ATT_SMEM>>>(qkvh, ah);

    // 3) out = attn @ Wout^T : [4096, 1024] -> fp32
    gemm_mma_f16<false><<<dim3(TOTDIM/128, MTOT/256), 256, GSMEM>>>(
        ah, woh, out, nullptr, TOTDIM, DMODEL);
}